// round 3
// baseline (speedup 1.0000x reference)
#include <cuda_runtime.h>

#define MAXN 4
#define MAXP 8192
#define BLOCK 128
#define RPT 8
#define TILE (BLOCK * RPT)   // 1024 outer points per block
#define CHUNK 1024           // inner points per block
#define FSPLIT 8
#define BLOCKF 256

typedef unsigned long long u64;

// SoA scratch: [coord][b*p + i], coord 0=x 1=y 2=z 3=h (h = 0.5*|p|^2; padded y -> 1e18)
__device__ __align__(16) float g_sx[4][MAXN * MAXP];
__device__ __align__(16) float g_sy[4][MAXN * MAXP];
__device__ unsigned g_minx[MAXN * MAXP];
__device__ unsigned g_miny[MAXN * MAXP];
__device__ float    g_part[MAXN][2][FSPLIT];
__device__ int      g_ctr;   // zero-initialized; last finalize block resets to 0

// ---- f32x2 packed helpers ------------------------------------------------
static __device__ __forceinline__ u64 pack2(float lo, float hi) {
    u64 r; asm("mov.b64 %0, {%1,%2};" : "=l"(r) : "f"(lo), "f"(hi)); return r;
}
static __device__ __forceinline__ u64 fma2(u64 a, u64 b, u64 c) {
    u64 d; asm("fma.rn.f32x2 %0, %1, %2, %3;" : "=l"(d) : "l"(a), "l"(b), "l"(c)); return d;
}
static __device__ __forceinline__ void unpack2(u64 v, float& lo, float& hi) {
    asm("mov.b64 {%0,%1}, %2;" : "=f"(lo), "=f"(hi) : "l"(v));
}

// Order-preserving float <-> uint mapping
static __device__ __forceinline__ unsigned fkey(float f) {
    unsigned u = __float_as_uint(f);
    return (u & 0x80000000u) ? ~u : (u | 0x80000000u);
}
static __device__ __forceinline__ float finv(unsigned u) {
    unsigned v = (u & 0x80000000u) ? (u ^ 0x80000000u) : ~u;
    return __uint_as_float(v);
}

// ---- pack: AoS xyz -> SoA {x,y,z,h}, init min keys -----------------------
__global__ void pack_kernel(const float* __restrict__ x, const float* __restrict__ y,
                            const int* __restrict__ lens, int n, int p1, int p2) {
    int idx = blockIdx.x * blockDim.x + threadIdx.x;
    if (idx < n * p1) {
        float a = x[3 * idx + 0], b = x[3 * idx + 1], c = x[3 * idx + 2];
        g_sx[0][idx] = a; g_sx[1][idx] = b; g_sx[2][idx] = c;
        g_sx[3][idx] = 0.5f * (a * a + b * b + c * c);
        g_minx[idx] = 0xFFFFFFFFu;
    }
    if (idx < n * p2) {
        int b_ = idx / p2;
        int j  = idx - b_ * p2;
        float a = y[3 * idx + 0], bb = y[3 * idx + 1], c = y[3 * idx + 2];
        float h = 0.5f * (a * a + bb * bb + c * c);
        g_sy[0][idx] = a; g_sy[1][idx] = bb; g_sy[2][idx] = c;
        g_sy[3][idx] = (j < lens[b_]) ? h : 1e18f;   // padded targets never win min
        g_miny[idx] = 0xFFFFFFFFu;
    }
}

// ---- fused both-direction pass ------------------------------------------
// blockIdx.z = batch*2 + dir. dir=0: outer=pred, inner=target. dir=1: outer=target, inner=pred.
// min_j d2 = 2*(h_outer + min_j (h_j - dot_ij)); inner math = 1.5 FFMA2 + 1 FMNMX per pair.
// Inner chunk loaded as ulonglong2 (two ready-made f32x2 register pairs, no pack movs).
__global__ void __launch_bounds__(BLOCK) pass_kernel(const int* __restrict__ lens,
                                                     int p1, int p2) {
    int zb  = blockIdx.z;
    int b   = zb >> 1;
    int dir = zb & 1;
    int len = __ldg(lens + b);

    int p_out = dir ? p2 : p1;
    int p_in  = dir ? p1 : p2;

    int tb = blockIdx.x * TILE;
    if (tb >= p_out) return;
    if (dir && tb >= len) return;                 // whole outer tile padded (dir1)

    int cb = blockIdx.y * CHUNK;
    int ilim = dir ? p_in : min(p_in, (len + 3) & ~3);   // dir0: clip inner to valid y
    if (cb >= ilim) return;
    int je = min(cb + CHUNK, ilim) >> 2;          // granules of 4 floats
    int jb0 = cb >> 2;

    const float (*ip)[MAXN * MAXP] = dir ? g_sx : g_sy;   // inner SoA
    const float (*op)[MAXN * MAXP] = dir ? g_sy : g_sx;   // outer SoA
    unsigned* mins = dir ? g_miny : g_minx;

    // Outer points: pre-negated, duplicated into both f32x2 lanes (built once).
    int obase = b * p_out + tb + threadIdx.x;
    u64 nx[RPT], ny[RPT], nz[RPT];
    float m[RPT];
#pragma unroll
    for (int r = 0; r < RPT; r++) {
        float a = op[0][obase + r * BLOCK];
        float bb = op[1][obase + r * BLOCK];
        float c = op[2][obase + r * BLOCK];
        nx[r] = pack2(-a, -a);
        ny[r] = pack2(-bb, -bb);
        nz[r] = pack2(-c, -c);
        m[r] = 3.4e38f;
    }

    // Each ulonglong2 = {f32x2(e0,e1), f32x2(e2,e3)} — direct FFMA2 operands.
    const ulonglong2* __restrict__ PX = (const ulonglong2*)&ip[0][b * p_in];
    const ulonglong2* __restrict__ PY = (const ulonglong2*)&ip[1][b * p_in];
    const ulonglong2* __restrict__ PZ = (const ulonglong2*)&ip[2][b * p_in];
    const ulonglong2* __restrict__ PH = (const ulonglong2*)&ip[3][b * p_in];

    for (int jb = jb0; jb < je; ++jb) {
        ulonglong2 vx = __ldg(PX + jb);
        ulonglong2 vy = __ldg(PY + jb);
        ulonglong2 vz = __ldg(PZ + jb);
        ulonglong2 vh = __ldg(PH + jb);
#pragma unroll
        for (int r = 0; r < RPT; r++) {
            u64 t = fma2(nx[r], vx.x, vh.x);       // {h - x*ox} for inner 0,1
            t = fma2(ny[r], vy.x, t);
            t = fma2(nz[r], vz.x, t);
            u64 s = fma2(nx[r], vx.y, vh.y);       // inner 2,3
            s = fma2(ny[r], vy.y, s);
            s = fma2(nz[r], vz.y, s);
            float tl, th, sl, sh;
            unpack2(t, tl, th);
            unpack2(s, sl, sh);
            m[r] = fminf(m[r], fminf(fminf(tl, th), fminf(sl, sh)));
        }
    }

#pragma unroll
    for (int r = 0; r < RPT; r++)
        atomicMin(&mins[obase + r * BLOCK], fkey(m[r]));  // padded outer rows harmless
}

// ---- fused finalize: partial sums + last-block deterministic combine -----
__global__ void finalize(float* __restrict__ out, const int* __restrict__ lens,
                         int n, int p1, int p2) {
    int b = blockIdx.x, dir = blockIdx.y, split = blockIdx.z;
    int p   = dir ? p2 : p1;
    int lim = dir ? __ldg(lens + b) : p1;
    int per = p / FSPLIT;
    int lo = split * per;
    int hi = min(lo + per, lim);
    const float* hs = dir ? g_sy[3] : g_sx[3];
    const unsigned* mins = dir ? g_miny : g_minx;

    __shared__ float sh[BLOCKF];
    float acc = 0.f;
    for (int i = lo + threadIdx.x; i < hi; i += BLOCKF) {
        float d2 = 2.f * (hs[b * p + i] + finv(mins[b * p + i]));
        acc += fmaxf(d2, 0.f);
    }
    sh[threadIdx.x] = acc;
    __syncthreads();
    for (int s = BLOCKF / 2; s > 0; s >>= 1) {
        if (threadIdx.x < s) sh[threadIdx.x] += sh[threadIdx.x + s];
        __syncthreads();
    }

    __shared__ int is_last;
    if (threadIdx.x == 0) {
        g_part[b][dir][split] = sh[0];
        __threadfence();
        int total = gridDim.x * gridDim.y * gridDim.z;
        is_last = (atomicAdd(&g_ctr, 1) == total - 1);
    }
    __syncthreads();
    if (!is_last) return;

    // Last block: deterministic fixed-order combine of all partials.
    __shared__ float per_bd[MAXN * 2];
    int t = threadIdx.x;
    if (t < n * 2) {
        int bb = t >> 1, dd = t & 1;
        float s = 0.f;
        for (int k = 0; k < FSPLIT; k++) s += g_part[bb][dd][k];
        per_bd[t] = s / (dd ? (float)__ldg(lens + bb) : (float)p1);
    }
    __syncthreads();
    if (t == 0) {
        float s = 0.f;
        for (int i = 0; i < n * 2; i++) s += per_bd[i];
        out[0] = s / (float)n;
        g_ctr = 0;  // reset for next graph replay
    }
}

extern "C" void kernel_launch(void* const* d_in, const int* in_sizes, int n_in,
                              void* d_out, int out_size) {
    const float* x   = (const float*)d_in[0];   // pred_points   [N,P1,3] f32
    const float* y   = (const float*)d_in[1];   // target_points [N,P2,3] f32
    const int*  lens = (const int*)d_in[2];     // target_lengths [N] i32
    // d_in[3] = num_neighbours == 1 (mean over K=1 is identity)

    int n  = in_sizes[2];
    int p1 = in_sizes[0] / (3 * n);
    int p2 = in_sizes[1] / (3 * n);
    int mx = p1 > p2 ? p1 : p2;

    pack_kernel<<<(n * mx + 255) / 256, 256>>>(x, y, lens, n, p1, p2);

    int tiles  = (mx + TILE - 1) / TILE;
    int chunks = (mx + CHUNK - 1) / CHUNK;
    dim3 g(tiles, chunks, n * 2);
    pass_kernel<<<g, BLOCK>>>(lens, p1, p2);

    finalize<<<dim3(n, 2, FSPLIT), BLOCKF>>>((float*)d_out, lens, n, p1, p2);
}

// round 4
// speedup vs baseline: 1.2309x; 1.2309x over previous
#include <cuda_runtime.h>

#define MAXN 4
#define MAXP 8192
#define BLOCK 128
#define RPT 8
#define TILE (BLOCK * RPT)   // 1024 outer points per block
#define CHUNK 512            // inner points per block
#define FSPLIT 8
#define BLOCKF 256

typedef unsigned long long u64;

// SoA scratch: [coord][b*p + i], coord 0=x 1=y 2=z 3=h (h = 0.5*|p|^2; padded y -> 1e18)
__device__ __align__(16) float g_sx[4][MAXN * MAXP];
__device__ __align__(16) float g_sy[4][MAXN * MAXP];
__device__ unsigned g_minx[MAXN * MAXP];
__device__ unsigned g_miny[MAXN * MAXP];
__device__ float    g_part[MAXN][2][FSPLIT];
__device__ int      g_ctr;

// ---- f32x2 packed helpers ------------------------------------------------
static __device__ __forceinline__ u64 pack2(float lo, float hi) {
    u64 r; asm("mov.b64 %0, {%1,%2};" : "=l"(r) : "f"(lo), "f"(hi)); return r;
}
static __device__ __forceinline__ u64 fma2(u64 a, u64 b, u64 c) {
    u64 d; asm("fma.rn.f32x2 %0, %1, %2, %3;" : "=l"(d) : "l"(a), "l"(b), "l"(c)); return d;
}
static __device__ __forceinline__ void unpack2(u64 v, float& lo, float& hi) {
    asm("mov.b64 {%0,%1}, %2;" : "=f"(lo), "=f"(hi) : "l"(v));
}

// Order-preserving float <-> uint mapping
static __device__ __forceinline__ unsigned fkey(float f) {
    unsigned u = __float_as_uint(f);
    return (u & 0x80000000u) ? ~u : (u | 0x80000000u);
}
static __device__ __forceinline__ float finv(unsigned u) {
    unsigned v = (u & 0x80000000u) ? (u ^ 0x80000000u) : ~u;
    return __uint_as_float(v);
}

// ---- pack kernels (split so that global launch idx 3 == pass_kernel) -----
__global__ void pack_x_kernel(const float* __restrict__ x, int n, int p1) {
    int idx = blockIdx.x * blockDim.x + threadIdx.x;
    if (idx < n * p1) {
        float a = x[3 * idx + 0], b = x[3 * idx + 1], c = x[3 * idx + 2];
        g_sx[0][idx] = a; g_sx[1][idx] = b; g_sx[2][idx] = c;
        g_sx[3][idx] = 0.5f * (a * a + b * b + c * c);
        g_minx[idx] = 0xFFFFFFFFu;
    }
}

__global__ void pack_y_kernel(const float* __restrict__ y,
                              const int* __restrict__ lens, int n, int p2) {
    int idx = blockIdx.x * blockDim.x + threadIdx.x;
    if (idx < n * p2) {
        int b_ = idx / p2;
        int j  = idx - b_ * p2;
        float a = y[3 * idx + 0], bb = y[3 * idx + 1], c = y[3 * idx + 2];
        float h = 0.5f * (a * a + bb * bb + c * c);
        g_sy[0][idx] = a; g_sy[1][idx] = bb; g_sy[2][idx] = c;
        g_sy[3][idx] = (j < lens[b_]) ? h : 1e18f;   // padded targets never win min
        g_miny[idx] = 0xFFFFFFFFu;
    }
}

__global__ void reset_kernel() {
    if (threadIdx.x == 0) g_ctr = 0;
}

// ---- fused both-direction pass ------------------------------------------
// blockIdx.z = batch*2 + dir. dir=0: outer=pred, inner=target. dir=1: outer=target, inner=pred.
// min_j d2 = 2*(h_outer + min_j (h_j - dot_ij))
__global__ void __launch_bounds__(BLOCK) pass_kernel(const int* __restrict__ lens,
                                                     int p1, int p2) {
    int zb  = blockIdx.z;
    int b   = zb >> 1;
    int dir = zb & 1;
    int len = __ldg(lens + b);

    int p_out = dir ? p2 : p1;
    int p_in  = dir ? p1 : p2;

    int tb = blockIdx.x * TILE;
    if (tb >= p_out) return;
    if (dir && tb >= len) return;                 // whole outer tile padded (dir1)

    int cb = blockIdx.y * CHUNK;
    int ilim = dir ? p_in : min(p_in, (len + 3) & ~3);   // dir0: clip inner to valid y
    if (cb >= ilim) return;
    int je = min(cb + CHUNK, ilim) >> 2;          // granules of 4 floats
    int jb0 = cb >> 2;

    const float (*ip)[MAXN * MAXP] = dir ? g_sx : g_sy;   // inner SoA
    const float (*op)[MAXN * MAXP] = dir ? g_sy : g_sx;   // outer SoA
    unsigned* mins = dir ? g_miny : g_minx;

    // Outer points: pre-negated, duplicated into both f32x2 lanes (built once).
    int obase = b * p_out + tb + threadIdx.x;
    u64 nx[RPT], ny[RPT], nz[RPT];
    float m[RPT];
#pragma unroll
    for (int r = 0; r < RPT; r++) {
        float a = op[0][obase + r * BLOCK];
        float bb = op[1][obase + r * BLOCK];
        float c = op[2][obase + r * BLOCK];
        nx[r] = pack2(-a, -a);
        ny[r] = pack2(-bb, -bb);
        nz[r] = pack2(-c, -c);
        m[r] = 3.4e38f;
    }

    // Each ulonglong2 = {f32x2(e0,e1), f32x2(e2,e3)} — direct FFMA2 operands.
    const ulonglong2* __restrict__ PX = (const ulonglong2*)&ip[0][b * p_in];
    const ulonglong2* __restrict__ PY = (const ulonglong2*)&ip[1][b * p_in];
    const ulonglong2* __restrict__ PZ = (const ulonglong2*)&ip[2][b * p_in];
    const ulonglong2* __restrict__ PH = (const ulonglong2*)&ip[3][b * p_in];

#pragma unroll 2
    for (int jb = jb0; jb < je; ++jb) {
        ulonglong2 vx = __ldg(PX + jb);
        ulonglong2 vy = __ldg(PY + jb);
        ulonglong2 vz = __ldg(PZ + jb);
        ulonglong2 vh = __ldg(PH + jb);
#pragma unroll
        for (int r = 0; r < RPT; r++) {
            u64 t = fma2(nx[r], vx.x, vh.x);       // {h - x*ox} for inner 0,1
            t = fma2(ny[r], vy.x, t);
            t = fma2(nz[r], vz.x, t);
            u64 s = fma2(nx[r], vx.y, vh.y);       // inner 2,3
            s = fma2(ny[r], vy.y, s);
            s = fma2(nz[r], vz.y, s);
            float tl, th, sl, sh;
            unpack2(t, tl, th);
            unpack2(s, sl, sh);
            m[r] = fminf(m[r], fminf(fminf(tl, th), fminf(sl, sh)));
        }
    }

#pragma unroll
    for (int r = 0; r < RPT; r++)
        atomicMin(&mins[obase + r * BLOCK], fkey(m[r]));  // padded outer rows harmless
}

// ---- fused finalize: partial sums + last-block deterministic combine -----
__global__ void finalize(float* __restrict__ out, const int* __restrict__ lens,
                         int n, int p1, int p2) {
    int b = blockIdx.x, dir = blockIdx.y, split = blockIdx.z;
    int p   = dir ? p2 : p1;
    int lim = dir ? __ldg(lens + b) : p1;
    int per = p / FSPLIT;
    int lo = split * per;
    int hi = min(lo + per, lim);
    const float* hs = dir ? g_sy[3] : g_sx[3];
    const unsigned* mins = dir ? g_miny : g_minx;

    __shared__ float sh[BLOCKF];
    float acc = 0.f;
    for (int i = lo + threadIdx.x; i < hi; i += BLOCKF) {
        float d2 = 2.f * (hs[b * p + i] + finv(mins[b * p + i]));
        acc += fmaxf(d2, 0.f);
    }
    sh[threadIdx.x] = acc;
    __syncthreads();
    for (int s = BLOCKF / 2; s > 0; s >>= 1) {
        if (threadIdx.x < s) sh[threadIdx.x] += sh[threadIdx.x + s];
        __syncthreads();
    }

    __shared__ int is_last;
    if (threadIdx.x == 0) {
        g_part[b][dir][split] = sh[0];
        __threadfence();
        int total = gridDim.x * gridDim.y * gridDim.z;
        is_last = (atomicAdd(&g_ctr, 1) == total - 1);
    }
    __syncthreads();
    if (!is_last) return;

    // Last block: deterministic fixed-order combine of all partials.
    __shared__ float per_bd[MAXN * 2];
    int t = threadIdx.x;
    if (t < n * 2) {
        int bb = t >> 1, dd = t & 1;
        float s = 0.f;
        for (int k = 0; k < FSPLIT; k++) s += g_part[bb][dd][k];
        per_bd[t] = s / (dd ? (float)__ldg(lens + bb) : (float)p1);
    }
    __syncthreads();
    if (t == 0) {
        float s = 0.f;
        for (int i = 0; i < n * 2; i++) s += per_bd[i];
        out[0] = s / (float)n;
    }
}

extern "C" void kernel_launch(void* const* d_in, const int* in_sizes, int n_in,
                              void* d_out, int out_size) {
    const float* x   = (const float*)d_in[0];   // pred_points   [N,P1,3] f32
    const float* y   = (const float*)d_in[1];   // target_points [N,P2,3] f32
    const int*  lens = (const int*)d_in[2];     // target_lengths [N] i32
    // d_in[3] = num_neighbours == 1 (mean over K=1 is identity)

    int n  = in_sizes[2];
    int p1 = in_sizes[0] / (3 * n);
    int p2 = in_sizes[1] / (3 * n);
    int mx = p1 > p2 ? p1 : p2;

    // Launch order chosen so GLOBAL LAUNCH INDEX 3 == pass_kernel (ncu -s 5
    // has landed on index 3 in every round so far).
    pack_x_kernel<<<(n * p1 + 255) / 256, 256>>>(x, n, p1);            // idx 0
    pack_y_kernel<<<(n * p2 + 255) / 256, 256>>>(y, lens, n, p2);      // idx 1
    reset_kernel<<<1, 32>>>();                                         // idx 2

    int tiles  = (mx + TILE - 1) / TILE;
    int chunks = (mx + CHUNK - 1) / CHUNK;
    dim3 g(tiles, chunks, n * 2);
    pass_kernel<<<g, BLOCK>>>(lens, p1, p2);                           // idx 3

    finalize<<<dim3(n, 2, FSPLIT), BLOCKF>>>((float*)d_out, lens, n, p1, p2);
}

// round 5
// speedup vs baseline: 1.3219x; 1.0739x over previous
#include <cuda_runtime.h>

#define MAXN 4
#define MAXP 8192
#define BLOCK 256
#define RPT 4
#define TILE (BLOCK * RPT)   // 1024 outer points per block
#define CHUNK 512            // inner points per block
#define FSPLIT 8
#define BLOCKF 256

typedef unsigned long long u64;

// SoA scratch: [coord][b*p + i], coord 0=x 1=y 2=z 3=h (h = 0.5*|p|^2; padded y -> 1e18)
__device__ __align__(16) float g_sx[4][MAXN * MAXP];
__device__ __align__(16) float g_sy[4][MAXN * MAXP];
__device__ unsigned g_minx[MAXN * MAXP];
__device__ unsigned g_miny[MAXN * MAXP];
__device__ float    g_part[MAXN][2][FSPLIT];
__device__ int      g_ctr;

// ---- f32x2 packed helpers ------------------------------------------------
static __device__ __forceinline__ u64 pack2(float lo, float hi) {
    u64 r; asm("mov.b64 %0, {%1,%2};" : "=l"(r) : "f"(lo), "f"(hi)); return r;
}
static __device__ __forceinline__ u64 fma2(u64 a, u64 b, u64 c) {
    u64 d; asm("fma.rn.f32x2 %0, %1, %2, %3;" : "=l"(d) : "l"(a), "l"(b), "l"(c)); return d;
}
static __device__ __forceinline__ void unpack2(u64 v, float& lo, float& hi) {
    asm("mov.b64 {%0,%1}, %2;" : "=f"(lo), "=f"(hi) : "l"(v));
}

// Order-preserving float <-> uint mapping
static __device__ __forceinline__ unsigned fkey(float f) {
    unsigned u = __float_as_uint(f);
    return (u & 0x80000000u) ? ~u : (u | 0x80000000u);
}
static __device__ __forceinline__ float finv(unsigned u) {
    unsigned v = (u & 0x80000000u) ? (u ^ 0x80000000u) : ~u;
    return __uint_as_float(v);
}

// ---- pack kernels (split so that global launch idx 3 == pass_kernel) -----
__global__ void pack_x_kernel(const float* __restrict__ x, int n, int p1) {
    int idx = blockIdx.x * blockDim.x + threadIdx.x;
    if (idx < n * p1) {
        float a = x[3 * idx + 0], b = x[3 * idx + 1], c = x[3 * idx + 2];
        g_sx[0][idx] = a; g_sx[1][idx] = b; g_sx[2][idx] = c;
        g_sx[3][idx] = 0.5f * (a * a + b * b + c * c);
        g_minx[idx] = 0xFFFFFFFFu;
    }
}

__global__ void pack_y_kernel(const float* __restrict__ y,
                              const int* __restrict__ lens, int n, int p2) {
    int idx = blockIdx.x * blockDim.x + threadIdx.x;
    if (idx < n * p2) {
        int b_ = idx / p2;
        int j  = idx - b_ * p2;
        float a = y[3 * idx + 0], bb = y[3 * idx + 1], c = y[3 * idx + 2];
        float h = 0.5f * (a * a + bb * bb + c * c);
        g_sy[0][idx] = a; g_sy[1][idx] = bb; g_sy[2][idx] = c;
        g_sy[3][idx] = (j < lens[b_]) ? h : 1e18f;   // padded targets never win min
        g_miny[idx] = 0xFFFFFFFFu;
    }
}

__global__ void reset_kernel() {
    if (threadIdx.x == 0) g_ctr = 0;
}

// ---- fused both-direction pass ------------------------------------------
// blockIdx.z = batch*2 + dir. dir=0: outer=pred, inner=target. dir=1: outer=target, inner=pred.
// min_j d2 = 2*(h_outer + min_j (h_j - dot_ij))
__global__ void __launch_bounds__(BLOCK, 4) pass_kernel(const int* __restrict__ lens,
                                                        int p1, int p2) {
    int zb  = blockIdx.z;
    int b   = zb >> 1;
    int dir = zb & 1;
    int len = __ldg(lens + b);

    int p_out = dir ? p2 : p1;
    int p_in  = dir ? p1 : p2;

    int tb = blockIdx.x * TILE;
    if (tb >= p_out) return;
    if (dir && tb >= len) return;                 // whole outer tile padded (dir1)

    int cb = blockIdx.y * CHUNK;
    int ilim = dir ? p_in : min(p_in, (len + 3) & ~3);   // dir0: clip inner to valid y
    if (cb >= ilim) return;
    int je = min(cb + CHUNK, ilim) >> 2;          // granules of 4 floats
    int jb0 = cb >> 2;

    const float (*ip)[MAXN * MAXP] = dir ? g_sx : g_sy;   // inner SoA
    const float (*op)[MAXN * MAXP] = dir ? g_sy : g_sx;   // outer SoA
    unsigned* mins = dir ? g_miny : g_minx;

    // Outer points: pre-negated, duplicated into both f32x2 lanes (built once).
    int obase = b * p_out + tb + threadIdx.x;
    u64 nx[RPT], ny[RPT], nz[RPT];
    float m[RPT];
#pragma unroll
    for (int r = 0; r < RPT; r++) {
        float a = op[0][obase + r * BLOCK];
        float bb = op[1][obase + r * BLOCK];
        float c = op[2][obase + r * BLOCK];
        nx[r] = pack2(-a, -a);
        ny[r] = pack2(-bb, -bb);
        nz[r] = pack2(-c, -c);
        m[r] = 3.4e38f;
    }

    // Each ulonglong2 = {f32x2(e0,e1), f32x2(e2,e3)} — direct FFMA2 operands.
    const ulonglong2* __restrict__ PX = (const ulonglong2*)&ip[0][b * p_in];
    const ulonglong2* __restrict__ PY = (const ulonglong2*)&ip[1][b * p_in];
    const ulonglong2* __restrict__ PZ = (const ulonglong2*)&ip[2][b * p_in];
    const ulonglong2* __restrict__ PH = (const ulonglong2*)&ip[3][b * p_in];

    for (int jb = jb0; jb < je; ++jb) {
        ulonglong2 vx = __ldg(PX + jb);
        ulonglong2 vy = __ldg(PY + jb);
        ulonglong2 vz = __ldg(PZ + jb);
        ulonglong2 vh = __ldg(PH + jb);
#pragma unroll
        for (int r = 0; r < RPT; r++) {
            u64 t = fma2(nx[r], vx.x, vh.x);       // {h - x*ox} for inner 0,1
            t = fma2(ny[r], vy.x, t);
            t = fma2(nz[r], vz.x, t);
            u64 s = fma2(nx[r], vx.y, vh.y);       // inner 2,3
            s = fma2(ny[r], vy.y, s);
            s = fma2(nz[r], vz.y, s);
            float tl, th, sl, sh;
            unpack2(t, tl, th);
            unpack2(s, sl, sh);
            m[r] = fminf(m[r], fminf(fminf(tl, th), fminf(sl, sh)));
        }
    }

#pragma unroll
    for (int r = 0; r < RPT; r++)
        atomicMin(&mins[obase + r * BLOCK], fkey(m[r]));  // padded outer rows harmless
}

// ---- fused finalize: partial sums + last-block deterministic combine -----
__global__ void finalize(float* __restrict__ out, const int* __restrict__ lens,
                         int n, int p1, int p2) {
    int b = blockIdx.x, dir = blockIdx.y, split = blockIdx.z;
    int p   = dir ? p2 : p1;
    int lim = dir ? __ldg(lens + b) : p1;
    int per = p / FSPLIT;
    int lo = split * per;
    int hi = min(lo + per, lim);
    const float* hs = dir ? g_sy[3] : g_sx[3];
    const unsigned* mins = dir ? g_miny : g_minx;

    __shared__ float sh[BLOCKF];
    float acc = 0.f;
    for (int i = lo + threadIdx.x; i < hi; i += BLOCKF) {
        float d2 = 2.f * (hs[b * p + i] + finv(mins[b * p + i]));
        acc += fmaxf(d2, 0.f);
    }
    sh[threadIdx.x] = acc;
    __syncthreads();
    for (int s = BLOCKF / 2; s > 0; s >>= 1) {
        if (threadIdx.x < s) sh[threadIdx.x] += sh[threadIdx.x + s];
        __syncthreads();
    }

    __shared__ int is_last;
    if (threadIdx.x == 0) {
        g_part[b][dir][split] = sh[0];
        __threadfence();
        int total = gridDim.x * gridDim.y * gridDim.z;
        is_last = (atomicAdd(&g_ctr, 1) == total - 1);
    }
    __syncthreads();
    if (!is_last) return;

    // Last block: deterministic fixed-order combine of all partials.
    __shared__ float per_bd[MAXN * 2];
    int t = threadIdx.x;
    if (t < n * 2) {
        int bb = t >> 1, dd = t & 1;
        float s = 0.f;
        for (int k = 0; k < FSPLIT; k++) s += g_part[bb][dd][k];
        per_bd[t] = s / (dd ? (float)__ldg(lens + bb) : (float)p1);
    }
    __syncthreads();
    if (t == 0) {
        float s = 0.f;
        for (int i = 0; i < n * 2; i++) s += per_bd[i];
        out[0] = s / (float)n;
    }
}

extern "C" void kernel_launch(void* const* d_in, const int* in_sizes, int n_in,
                              void* d_out, int out_size) {
    const float* x   = (const float*)d_in[0];   // pred_points   [N,P1,3] f32
    const float* y   = (const float*)d_in[1];   // target_points [N,P2,3] f32
    const int*  lens = (const int*)d_in[2];     // target_lengths [N] i32
    // d_in[3] = num_neighbours == 1 (mean over K=1 is identity)

    int n  = in_sizes[2];
    int p1 = in_sizes[0] / (3 * n);
    int p2 = in_sizes[1] / (3 * n);
    int mx = p1 > p2 ? p1 : p2;

    // Launch order keeps GLOBAL LAUNCH INDEX 3 == pass_kernel (ncu -s 5).
    pack_x_kernel<<<(n * p1 + 255) / 256, 256>>>(x, n, p1);            // idx 0
    pack_y_kernel<<<(n * p2 + 255) / 256, 256>>>(y, lens, n, p2);      // idx 1
    reset_kernel<<<1, 32>>>();                                         // idx 2

    int tiles  = (mx + TILE - 1) / TILE;
    int chunks = (mx + CHUNK - 1) / CHUNK;
    dim3 g(tiles, chunks, n * 2);
    pass_kernel<<<g, BLOCK>>>(lens, p1, p2);                           // idx 3

    finalize<<<dim3(n, 2, FSPLIT), BLOCKF>>>((float*)d_out, lens, n, p1, p2);
}